// round 8
// baseline (speedup 1.0000x reference)
#include <cuda_runtime.h>

// LoCon1d: out[b][o][s] = bias[o][s] + sum_{c,k} in[b][c][s+k-1] * w[o][c][s][k]
// input (16,64,1024) f32, weight (64,64,1024,3) f32, bias (64,1024) f32, out (16,64,1024) f32
// Strategy: transpose input to (Cin, S, B) so batch is contiguous; then one thread
// per (o, s) accumulates all 16 batches with vectorized float4 loads over batch.

#define CIN   64
#define COUT  64
#define SLEN  1024
#define BATCH 16

// 4 MB device scratch for transposed input: in_t[c][s][b]
__device__ float g_in_t[CIN * SLEN * BATCH];

__global__ __launch_bounds__(256)
void transpose_kernel(const float* __restrict__ in)
{
    const int idx = blockIdx.x * 256 + threadIdx.x;  // 0..65535 -> (c, s)
    const int c = idx >> 10;
    const int s = idx & (SLEN - 1);

    float t[BATCH];
#pragma unroll
    for (int b = 0; b < BATCH; b++)
        t[b] = in[((size_t)b * CIN + c) * SLEN + s];

    float4* dst = (float4*)&g_in_t[(size_t)idx * BATCH];
#pragma unroll
    for (int i = 0; i < 4; i++)
        dst[i] = make_float4(t[4 * i], t[4 * i + 1], t[4 * i + 2], t[4 * i + 3]);
}

#define OPB 8   // couts per CTA (one warp each)
#define SPB 32  // s positions per CTA (one per lane)

__global__ __launch_bounds__(256)
void locon_main(const float* __restrict__ weight,
                const float* __restrict__ bias,
                float* __restrict__ out)
{
    const int s = blockIdx.x * SPB + (threadIdx.x & 31);   // lane -> s
    const int o = blockIdx.y * OPB + (threadIdx.x >> 5);   // warp -> o

    // boundary masks: s==0 kills the k=0 tap, s==SLEN-1 kills the k=2 tap
    const float maskl = (s > 0)        ? 1.0f : 0.0f;
    const float maskr = (s < SLEN - 1) ? 1.0f : 0.0f;
    const int   offm  = (s > 0)        ? -BATCH : 0;  // clamped (value masked anyway)
    const int   offp  = (s < SLEN - 1) ?  BATCH : 0;

    float4 acc[4];
#pragma unroll
    for (int i = 0; i < 4; i++) acc[i] = make_float4(0.f, 0.f, 0.f, 0.f);

    // weight[(o*CIN + c)*SLEN + s]*3 ; per-c stride = SLEN*3 floats
    const float* wp = weight + ((size_t)o * CIN * SLEN + s) * 3;
    // in_t row (c, s): per-c stride = SLEN*BATCH floats
    const float* ip = g_in_t + (size_t)s * BATCH;

#pragma unroll 2
    for (int c = 0; c < CIN; c++) {
        const float w0 = wp[0] * maskl;
        const float w1 = wp[1];
        const float w2 = wp[2] * maskr;

        const float4* rm = (const float4*)(ip + offm);  // row s-1 (16 b)
        const float4* r0 = (const float4*)(ip);         // row s
        const float4* rp = (const float4*)(ip + offp);  // row s+1

#pragma unroll
        for (int i = 0; i < 4; i++) {
            const float4 m = rm[i];
            const float4 z = r0[i];
            const float4 p = rp[i];
            acc[i].x = fmaf(m.x, w0, fmaf(z.x, w1, fmaf(p.x, w2, acc[i].x)));
            acc[i].y = fmaf(m.y, w0, fmaf(z.y, w1, fmaf(p.y, w2, acc[i].y)));
            acc[i].z = fmaf(m.z, w0, fmaf(z.z, w1, fmaf(p.z, w2, acc[i].z)));
            acc[i].w = fmaf(m.w, w0, fmaf(z.w, w1, fmaf(p.w, w2, acc[i].w)));
        }

        wp += SLEN * 3;
        ip += (size_t)SLEN * BATCH;
    }

    const float bv = bias[(size_t)o * SLEN + s];
    float r[BATCH] = {
        acc[0].x + bv, acc[0].y + bv, acc[0].z + bv, acc[0].w + bv,
        acc[1].x + bv, acc[1].y + bv, acc[1].z + bv, acc[1].w + bv,
        acc[2].x + bv, acc[2].y + bv, acc[2].z + bv, acc[2].w + bv,
        acc[3].x + bv, acc[3].y + bv, acc[3].z + bv, acc[3].w + bv
    };

#pragma unroll
    for (int b = 0; b < BATCH; b++)
        out[((size_t)b * COUT + o) * SLEN + s] = r[b];
}

extern "C" void kernel_launch(void* const* d_in, const int* in_sizes, int n_in,
                              void* d_out, int out_size)
{
    const float* input  = (const float*)d_in[0];  // (16, 64, 1024)
    const float* weight = (const float*)d_in[1];  // (64, 64, 1024, 3)
    const float* bias   = (const float*)d_in[2];  // (64, 1024)
    float* out = (float*)d_out;                   // (16, 64, 1024)

    transpose_kernel<<<CIN * SLEN / 256, 256>>>(input);

    dim3 grid(SLEN / SPB, COUT / OPB);  // 32 x 8 = 256 CTAs, 256 thr
    locon_main<<<grid, 256>>>(weight, bias, out);
}

// round 9
// speedup vs baseline: 2.4434x; 2.4434x over previous
#include <cuda_runtime.h>

// LoCon1d: out[b][o][s] = bias[o][s] + sum_{c,k} in[b][c][s+k-1] * w[o][c][s][k]
// input (16,64,1024) f32, weight (64,64,1024,3) f32, bias (64,1024) f32, out (16,64,1024) f32
//
// CTA: one 8-wide s-tile, all 64 couts, all 16 batches, full c-reduction.
// Input tile staged (transposed) in smem: logical [c][j][b], j = s_local+1+(-1..+8).
// Swizzle: the 4-float b-group i of row j lives at slot (i + (j>>1)) & 3  -> conflict-free
// LDS.128 across 8 consecutive rows without padding (40 KB total).
// Math uses packed fp32x2 FMA (fma.rn.f32x2) over batch pairs.

#define CIN   64
#define COUT  64
#define SLEN  1024
#define BATCH 16
#define SP    8          // s positions per CTA
#define JROWS (SP + 2)   // input rows needed (halo)
#define TPB   512

__device__ __forceinline__ unsigned long long pack2(float w) {
    unsigned long long r;
    asm("mov.b64 %0, {%1, %1};" : "=l"(r) : "f"(w));
    return r;
}
__device__ __forceinline__ void fma2(unsigned long long& a,
                                     unsigned long long x,
                                     unsigned long long w) {
    asm("fma.rn.f32x2 %0, %1, %2, %0;" : "+l"(a) : "l"(x), "l"(w));
}
__device__ __forceinline__ float2 unpack2(unsigned long long a) {
    float2 f;
    asm("mov.b64 {%0, %1}, %2;" : "=f"(f.x), "=f"(f.y) : "l"(a));
    return f;
}

__global__ __launch_bounds__(TPB)
void locon_smem(const float* __restrict__ input,
                const float* __restrict__ weight,
                const float* __restrict__ bias,
                float* __restrict__ out)
{
    __shared__ float sm[CIN * JROWS * BATCH];  // 40960 B, swizzled

    const int s0 = blockIdx.x * SP;

    // ---- fill: transpose input tile into smem ----
    // pair p -> (b = p & 15, c = p >> 4); each pair writes JROWS scalars.
#pragma unroll
    for (int it = 0; it < 2; it++) {
        const int p = threadIdx.x + it * TPB;       // 0..1023
        const int b = p & 15;
        const int c = p >> 4;
        const float* gin = input + ((size_t)b * CIN + c) * SLEN;
        const int bg   = b >> 2;      // b-group 0..3
        const int bsub = b & 3;
#pragma unroll
        for (int j = 0; j < JROWS; j++) {
            const int gs = s0 - 1 + j;
            const float v = (gs >= 0 && gs < SLEN) ? gin[gs] : 0.0f;
            const int slot = ((bg + (j >> 1)) & 3) * 4 + bsub;
            sm[(c * JROWS + j) * BATCH + slot] = v;
        }
    }
    __syncthreads();

    // ---- compute: thread = (o, sl), all 16 batches ----
    const int o  = threadIdx.x >> 3;     // 0..63
    const int sl = threadIdx.x & 7;      // 0..7
    const int sg = s0 + sl;

    unsigned long long acc[8];
#pragma unroll
    for (int i = 0; i < 8; i++) acc[i] = 0ULL;

    const float* wp = weight + ((size_t)o * CIN * SLEN + sg) * 3;
    float w0 = wp[0], w1 = wp[1], w2 = wp[2];

    for (int c = 0; c < CIN; c++) {
        // prefetch next c's weights (hide streaming latency)
        float n0 = 0.f, n1 = 0.f, n2 = 0.f;
        if (c < CIN - 1) {
            const float* np = wp + SLEN * 3;
            n0 = np[0]; n1 = np[1]; n2 = np[2];
        }

        const unsigned long long W0 = pack2(w0);
        const unsigned long long W1 = pack2(w1);
        const unsigned long long W2 = pack2(w2);

        const float* base = sm + c * (JROWS * BATCH);
#pragma unroll
        for (int k = 0; k < 3; k++) {
            const int j = sl + k;                     // input row
            const float* rowb = base + j * BATCH;
            const int half = j >> 1;
            const unsigned long long Wk = (k == 0) ? W0 : (k == 1) ? W1 : W2;
#pragma unroll
            for (int i = 0; i < 4; i++) {             // b-group
                const ulonglong2 v =
                    *(const ulonglong2*)(rowb + ((i + half) & 3) * 4);
                fma2(acc[2 * i],     v.x, Wk);
                fma2(acc[2 * i + 1], v.y, Wk);
            }
        }

        w0 = n0; w1 = n1; w2 = n2;
        wp += SLEN * 3;
    }

    // ---- bias + store ----
    const float bv = bias[(size_t)o * SLEN + sg];
#pragma unroll
    for (int i = 0; i < 4; i++) {
        const float2 lo = unpack2(acc[2 * i]);
        const float2 hi = unpack2(acc[2 * i + 1]);
        const int b0 = 4 * i;
        out[((size_t)(b0 + 0) * COUT + o) * SLEN + sg] = lo.x + bv;
        out[((size_t)(b0 + 1) * COUT + o) * SLEN + sg] = lo.y + bv;
        out[((size_t)(b0 + 2) * COUT + o) * SLEN + sg] = hi.x + bv;
        out[((size_t)(b0 + 3) * COUT + o) * SLEN + sg] = hi.y + bv;
    }
}

extern "C" void kernel_launch(void* const* d_in, const int* in_sizes, int n_in,
                              void* d_out, int out_size)
{
    const float* input  = (const float*)d_in[0];  // (16, 64, 1024)
    const float* weight = (const float*)d_in[1];  // (64, 64, 1024, 3)
    const float* bias   = (const float*)d_in[2];  // (64, 1024)
    float* out = (float*)d_out;                   // (16, 64, 1024)

    locon_smem<<<SLEN / SP, TPB>>>(input, weight, bias, out);  // 128 CTAs x 512
}